// round 1
// baseline (speedup 1.0000x reference)
#include <cuda_runtime.h>
#include <cuda_bf16.h>

// ---------------------------------------------------------------------------
// SDGNN forward: L layers, each = [x | GAT_r(x) for r in 0..R-1] -> tanh MLP
// Shapes (from setup_inputs): N=100000, D=64, E=1e6, L=2, R=4.
// Scratch lives in __device__ globals (no allocation allowed).
// ---------------------------------------------------------------------------

#define MAXN 100000
#define DD   64

__device__ __align__(16) float g_x[(size_t)MAXN * DD];        // current layer input
__device__ __align__(16) float g_h[(size_t)MAXN * DD];        // h = x @ Wg[l,r]
__device__ __align__(16) float g_comb[(size_t)MAXN * 5 * DD]; // [x | gat0..gat3]
__device__ float g_as[MAXN];
__device__ float g_ad[MAXN];
__device__ float g_m[MAXN];
__device__ float g_den[MAXN];
__device__ int   g_is64;   // 1 if edges are int64, 0 if int32

// ---------------------------------------------------------------------------
// Detect edge dtype: values are in [0, N) so if int64, every high u32 word = 0.
// ---------------------------------------------------------------------------
__global__ void detect_kernel(const unsigned int* __restrict__ e) {
    int odd_nonzero = 0;
    for (int i = 1; i < 512; i += 2)
        if (e[i] != 0u) odd_nonzero = 1;
    g_is64 = odd_nonzero ? 0 : 1;
}

__device__ __forceinline__ void load_edge(const void* edges, int r, long long E,
                                          int i, int n, int& s, int& d) {
    if (i < (int)E) {
        if (g_is64) {
            const long long* p = (const long long*)edges;
            s = (int)p[(long long)(2 * r) * E + i];
            d = (int)p[(long long)(2 * r + 1) * E + i];
        } else {
            const int* p = (const int*)edges;
            s = p[(long long)(2 * r) * E + i];
            d = p[(long long)(2 * r + 1) * E + i];
        }
    } else {
        s = d = i - (int)E;   // self loop
    }
    (void)n;
}

// ---------------------------------------------------------------------------
// Simple copies / init
// ---------------------------------------------------------------------------
__global__ void copy_in_kernel(const float* __restrict__ xin, long long cnt) {
    long long i = (long long)blockIdx.x * blockDim.x + threadIdx.x;
    if (i < cnt) g_x[i] = xin[i];
}

__global__ void copyx_comb_kernel(int n) {
    long long i = (long long)blockIdx.x * blockDim.x + threadIdx.x;
    if (i >= (long long)n * DD) return;
    int row = (int)(i >> 6);
    int j   = (int)(i & 63);
    g_comb[(long long)row * (5 * DD) + j] = g_x[i];
}

// per (layer, relation): zero alphas/denominator, set m=-inf, seed comb slice with bias
__global__ void rel_init_kernel(const float* __restrict__ bg, int coloff, int n) {
    long long i = (long long)blockIdx.x * blockDim.x + threadIdx.x;
    if (i >= (long long)n * DD) return;
    int row = (int)(i >> 6);
    int j   = (int)(i & 63);
    g_comb[(long long)row * (5 * DD) + coloff + j] = bg[j];
    if (j == 0) {
        g_as[row]  = 0.f;
        g_ad[row]  = 0.f;
        g_m[row]   = __int_as_float(0xff800000); // -inf
        g_den[row] = 0.f;
    }
}

// ---------------------------------------------------------------------------
// h = x @ W  fused with alpha_s = h@a_src, alpha_d = h@a_dst
// Block: 256 threads = 4 row-groups x 64 cols. W column held in registers.
// ---------------------------------------------------------------------------
__global__ void gemm_h_kernel(const float* __restrict__ W,
                              const float* __restrict__ avs,
                              const float* __restrict__ avd, int n) {
    __shared__ float xs[4][DD];
    int col = threadIdx.x & 63;
    int g   = threadIdx.x >> 6;

    float w[DD];
#pragma unroll
    for (int k = 0; k < DD; k++) w[k] = W[k * DD + col];
    float a_s = avs[col];
    float a_d = avd[col];

    for (long long base = (long long)blockIdx.x * 4; base < n;
         base += (long long)gridDim.x * 4) {
        int row = (int)base + g;
        __syncthreads();
        if (row < n) xs[g][col] = g_x[(long long)row * DD + col];
        __syncthreads();
        if (row < n) {
            float acc = 0.f;
            const float4* xv4 = (const float4*)xs[g];
#pragma unroll
            for (int k4 = 0; k4 < 16; k4++) {
                float4 xv = xv4[k4];
                acc += xv.x * w[4 * k4 + 0] + xv.y * w[4 * k4 + 1] +
                       xv.z * w[4 * k4 + 2] + xv.w * w[4 * k4 + 3];
            }
            g_h[(long long)row * DD + col] = acc;

            float vs = acc * a_s;
            float vd = acc * a_d;
#pragma unroll
            for (int off = 16; off; off >>= 1) {
                vs += __shfl_down_sync(0xffffffffu, vs, off);
                vd += __shfl_down_sync(0xffffffffu, vd, off);
            }
            if ((threadIdx.x & 31) == 0) {
                atomicAdd(&g_as[row], vs);
                atomicAdd(&g_ad[row], vd);
            }
        }
    }
}

// ---------------------------------------------------------------------------
// Edge passes (E real edges + N self loops)
// ---------------------------------------------------------------------------
__global__ void edge_max_kernel(const void* edges, int r, long long E, int n) {
    int i = blockIdx.x * blockDim.x + threadIdx.x;
    int T = (int)E + n;
    if (i >= T) return;
    int s, d;
    load_edge(edges, r, E, i, n, s, d);
    float e = g_as[s] + g_ad[d];
    e = e > 0.f ? e : 0.2f * e;
    if (e >= 0.f) atomicMax((int*)&g_m[d], __float_as_int(e));
    else          atomicMin((unsigned int*)&g_m[d], __float_as_uint(e));
}

__global__ void edge_sum_kernel(const void* edges, int r, long long E, int n) {
    int i = blockIdx.x * blockDim.x + threadIdx.x;
    int T = (int)E + n;
    if (i >= T) return;
    int s, d;
    load_edge(edges, r, E, i, n, s, d);
    float e = g_as[s] + g_ad[d];
    e = e > 0.f ? e : 0.2f * e;
    atomicAdd(&g_den[d], __expf(e - g_m[d]));
}

// Aggregation: 16 lanes per edge, each doing one float4 gather + vector red.
__global__ void edge_agg_kernel(const void* edges, int r, long long E, int n,
                                int coloff4) {
    int gt   = blockIdx.x * blockDim.x + threadIdx.x;
    int lane = gt & 31;
    int sub  = lane & 15;
    int i    = ((gt >> 5) << 1) + (lane >> 4);
    int T = (int)E + n;
    if (i >= T) return;
    int s, d;
    load_edge(edges, r, E, i, n, s, d);
    float e = g_as[s] + g_ad[d];
    e = e > 0.f ? e : 0.2f * e;
    float coef = __fdividef(__expf(e - g_m[d]), g_den[d]);

    const float4* h4 = (const float4*)g_h;
    float4 hv = h4[(long long)s * 16 + sub];
    float4* dstp = ((float4*)g_comb) + (long long)d * 80 + coloff4 + sub;
    asm volatile("red.global.add.v4.f32 [%0], {%1,%2,%3,%4};"
                 :: "l"(dstp), "f"(hv.x * coef), "f"(hv.y * coef),
                    "f"(hv.z * coef), "f"(hv.w * coef)
                 : "memory");
}

// ---------------------------------------------------------------------------
// MLP: out = tanh(comb @ W1 + b1) @ W2 + b2
// Block: 512 threads = 8 groups x 64 cols; 64-row tile; 8 rows per thread.
// smem: W1 (80KB) + W2 (16KB) + comb tile (80KB) + hidden tile (16KB) = 192KB
// ---------------------------------------------------------------------------
__global__ void mlp_kernel(const float* __restrict__ W1,
                           const float* __restrict__ b1,
                           const float* __restrict__ W2,
                           const float* __restrict__ b2,
                           float* __restrict__ outbuf, int last, int n) {
    extern __shared__ float sm[];
    float* W1s   = sm;                    // 320*64
    float* W2s   = W1s + 320 * 64;        // 64*64
    float* combs = W2s + 64 * 64;         // 64*320
    float* hids  = combs + 64 * 320;      // 64*64

    int tid = threadIdx.x;
    int col = tid & 63;
    int g   = tid >> 6;

    for (int i = tid; i < 320 * 64; i += 512) W1s[i] = W1[i];
    for (int i = tid; i < 64 * 64; i += 512)  W2s[i] = W2[i];
    float b1c = b1[col];
    float b2c = b2[col];

    long long base = (long long)blockIdx.x * 64 * 320;
    long long lim  = (long long)n * 320;
    for (int i = tid; i < 64 * 320; i += 512)
        combs[i] = (base + i < lim) ? g_comb[base + i] : 0.f;
    __syncthreads();

    float acc[8];
#pragma unroll
    for (int q = 0; q < 8; q++) acc[q] = 0.f;
    const float4* c4 = (const float4*)(combs + g * 8 * 320);
#pragma unroll 4
    for (int k4 = 0; k4 < 80; k4++) {
        float w0 = W1s[(4 * k4 + 0) * 64 + col];
        float w1 = W1s[(4 * k4 + 1) * 64 + col];
        float w2 = W1s[(4 * k4 + 2) * 64 + col];
        float w3 = W1s[(4 * k4 + 3) * 64 + col];
#pragma unroll
        for (int q = 0; q < 8; q++) {
            float4 cv = c4[q * 80 + k4];
            acc[q] += cv.x * w0 + cv.y * w1 + cv.z * w2 + cv.w * w3;
        }
    }
#pragma unroll
    for (int q = 0; q < 8; q++)
        hids[(g * 8 + q) * 64 + col] = tanhf(acc[q] + b1c);
    __syncthreads();

    float acc2[8];
#pragma unroll
    for (int q = 0; q < 8; q++) acc2[q] = 0.f;
    const float4* h4 = (const float4*)(hids + g * 8 * 64);
#pragma unroll
    for (int k4 = 0; k4 < 16; k4++) {
        float w0 = W2s[(4 * k4 + 0) * 64 + col];
        float w1 = W2s[(4 * k4 + 1) * 64 + col];
        float w2 = W2s[(4 * k4 + 2) * 64 + col];
        float w3 = W2s[(4 * k4 + 3) * 64 + col];
#pragma unroll
        for (int q = 0; q < 8; q++) {
            float4 hv = h4[q * 16 + k4];
            acc2[q] += hv.x * w0 + hv.y * w1 + hv.z * w2 + hv.w * w3;
        }
    }

    float* o = last ? outbuf : g_x;
    int row0 = blockIdx.x * 64 + g * 8;
#pragma unroll
    for (int q = 0; q < 8; q++) {
        int row = row0 + q;
        if (row < n) o[(long long)row * 64 + col] = acc2[q] + b2c;
    }
}

// ---------------------------------------------------------------------------
// Host orchestration (graph-capturable: kernel launches only, default stream)
// ---------------------------------------------------------------------------
extern "C" void kernel_launch(void* const* d_in, const int* in_sizes, int n_in,
                              void* d_out, int out_size) {
    const float* x_in  = (const float*)d_in[0];
    const void*  edges = d_in[1];
    const float* Wg    = (const float*)d_in[2];
    const float* a_src = (const float*)d_in[3];
    const float* a_dst = (const float*)d_in[4];
    const float* bg    = (const float*)d_in[5];
    const float* W1    = (const float*)d_in[6];
    const float* b1    = (const float*)d_in[7];
    const float* W2    = (const float*)d_in[8];
    const float* b2    = (const float*)d_in[9];

    int D  = in_sizes[2] / in_sizes[3];   // Wg:(L*R*D*D) / a_src:(L*R*D)
    int LD = in_sizes[7];                 // b1 = L*D
    int L  = LD / D;
    int R  = in_sizes[3] / LD;            // a_src / (L*D)
    int N  = in_sizes[0] / D;
    long long E = (long long)in_sizes[1] / (2 * R);

    cudaFuncSetAttribute(mlp_kernel,
                         cudaFuncAttributeMaxDynamicSharedMemorySize, 196608);

    detect_kernel<<<1, 1>>>((const unsigned int*)edges);

    long long nd = (long long)N * D;
    int nb_nd = (int)((nd + 255) / 256);
    copy_in_kernel<<<nb_nd, 256>>>(x_in, nd);

    int T = (int)E + N;
    int nb_edge = (T + 255) / 256;
    long long lanes = (long long)T * 16;
    int nb_agg = (int)((lanes + 255) / 256);
    int nb_gemm = 1480;  // grid-stride: amortize W register loads over many rows

    for (int l = 0; l < L; l++) {
        copyx_comb_kernel<<<nb_nd, 256>>>(N);
        for (int r = 0; r < R; r++) {
            rel_init_kernel<<<nb_nd, 256>>>(bg + ((long long)l * R + r) * D,
                                            (1 + r) * D, N);
            gemm_h_kernel<<<nb_gemm, 256>>>(Wg + ((long long)l * R + r) * D * D,
                                            a_src + ((long long)l * R + r) * D,
                                            a_dst + ((long long)l * R + r) * D, N);
            edge_max_kernel<<<nb_edge, 256>>>(edges, r, E, N);
            edge_sum_kernel<<<nb_edge, 256>>>(edges, r, E, N);
            edge_agg_kernel<<<nb_agg, 256>>>(edges, r, E, N, (1 + r) * 16);
        }
        mlp_kernel<<<(N + 63) / 64, 512, 196608>>>(
            W1 + (long long)l * 5 * D * D, b1 + (long long)l * D,
            W2 + (long long)l * D * D, b2 + (long long)l * D,
            (float*)d_out, (l == L - 1) ? 1 : 0, N);
    }
}

// round 3
// speedup vs baseline: 1.0937x; 1.0937x over previous
#include <cuda_runtime.h>

// ---------------------------------------------------------------------------
// SDGNN forward. N=100000, D=64, E=1e6, L=2, R=4.
// R1-proven structure + single fused edge pass per relation using the
// globally-shifted softmax (shift-invariance), normalization as its own pass.
// ---------------------------------------------------------------------------

#define MAXN 100000
#define MAXE 1000000
#define DD   64

__device__ __align__(16) float g_x[(size_t)MAXN * DD];         // layer activations
__device__ __align__(16) float g_h[(size_t)MAXN * DD];         // h = x @ Wg[l,r]
__device__ __align__(16) float g_comb[(size_t)MAXN * 5 * DD];  // [x | gat0..gat3]
__device__ __align__(16) int2  g_e[(size_t)4 * MAXE];          // packed int32 edges
__device__ float g_as[MAXN];
__device__ float g_ad[MAXN];
__device__ float g_den[(size_t)4 * MAXN];                      // per-relation denominators
__device__ int   g_ms[4];                                      // float-as-int max trackers
__device__ int   g_md[4];
__device__ int   g_is64;

// ---------------------------------------------------------------------------
__global__ void detect_kernel(const unsigned int* __restrict__ e) {
    int odd_nonzero = 0;
    for (int i = 1; i < 512; i += 2)
        if (e[i] != 0u) odd_nonzero = 1;
    g_is64 = odd_nonzero ? 0 : 1;
}

__global__ void pack_edges_kernel(const void* __restrict__ edges, long long E, int R) {
    long long i = (long long)blockIdx.x * blockDim.x + threadIdx.x;
    long long tot = (long long)R * E;
    if (i >= tot) return;
    int r = (int)(i / E);
    long long j = i - (long long)r * E;
    int s, d;
    if (g_is64) {
        const long long* p = (const long long*)edges;
        s = (int)p[(long long)(2 * r) * E + j];
        d = (int)p[(long long)(2 * r + 1) * E + j];
    } else {
        const int* p = (const int*)edges;
        s = p[(long long)(2 * r) * E + j];
        d = p[(long long)(2 * r + 1) * E + j];
    }
    g_e[(size_t)r * MAXE + j] = make_int2(s, d);
}

// ---------------------------------------------------------------------------
__global__ void copy_in_kernel(const float* __restrict__ xin, long long cnt) {
    long long i = (long long)blockIdx.x * blockDim.x + threadIdx.x;
    if (i < cnt) g_x[i] = xin[i];
}

// comb[:, 0:64] = g_x, comb[:, 64:320] = 0   (float4 granularity: 80 per row)
__global__ void comb_init_kernel(int n) {
    long long i = (long long)blockIdx.x * blockDim.x + threadIdx.x;
    if (i >= (long long)n * 80) return;
    int row = (int)(i / 80);
    int c   = (int)(i - (long long)row * 80);
    float4 v;
    if (c < 16) v = ((const float4*)g_x)[(size_t)row * 16 + c];
    else        v = make_float4(0.f, 0.f, 0.f, 0.f);
    ((float4*)g_comb)[i] = v;
}

__global__ void zero_den_kernel(int R) {
    long long i = (long long)blockIdx.x * blockDim.x + threadIdx.x;
    if (i < (long long)R * MAXN) g_den[i] = 0.f;
    if (i < 4) { g_ms[i] = 0xff800000; g_md[i] = 0xff800000; }
}

__global__ void zero_alpha_kernel(int n) {
    int i = blockIdx.x * blockDim.x + threadIdx.x;
    if (i < n) { g_as[i] = 0.f; g_ad[i] = 0.f; }
}

// ---------------------------------------------------------------------------
// h = x @ W fused with alpha_s/alpha_d (R1-proven version, atomicAdd alphas)
// ---------------------------------------------------------------------------
__global__ void gemm_h_kernel(const float* __restrict__ W,
                              const float* __restrict__ avs,
                              const float* __restrict__ avd, int n) {
    __shared__ float xs[4][DD];
    int col = threadIdx.x & 63;
    int g   = threadIdx.x >> 6;

    float w[DD];
#pragma unroll
    for (int k = 0; k < DD; k++) w[k] = W[k * DD + col];
    float a_s = avs[col];
    float a_d = avd[col];

    for (long long base = (long long)blockIdx.x * 4; base < n;
         base += (long long)gridDim.x * 4) {
        int row = (int)base + g;
        __syncthreads();
        if (row < n) xs[g][col] = g_x[(long long)row * DD + col];
        __syncthreads();
        if (row < n) {
            float acc = 0.f;
            const float4* xv4 = (const float4*)xs[g];
#pragma unroll
            for (int k4 = 0; k4 < 16; k4++) {
                float4 xv = xv4[k4];
                acc += xv.x * w[4 * k4 + 0] + xv.y * w[4 * k4 + 1] +
                       xv.z * w[4 * k4 + 2] + xv.w * w[4 * k4 + 3];
            }
            g_h[(long long)row * DD + col] = acc;

            float vs = acc * a_s;
            float vd = acc * a_d;
#pragma unroll
            for (int off = 16; off; off >>= 1) {
                vs += __shfl_down_sync(0xffffffffu, vs, off);
                vd += __shfl_down_sync(0xffffffffu, vd, off);
            }
            if ((threadIdx.x & 31) == 0) {
                atomicAdd(&g_as[row], vs);
                atomicAdd(&g_ad[row], vd);
            }
        }
    }
}

// ---------------------------------------------------------------------------
// Global max of alpha_s and alpha_d for relation r
// ---------------------------------------------------------------------------
__device__ __forceinline__ void atomic_fmax(int* addr, float v) {
    if (v >= 0.f) atomicMax(addr, __float_as_int(v));
    else          atomicMin((unsigned int*)addr, __float_as_uint(v));
}

__global__ void maxred_kernel(int r, int n) {
    float ms = -1e30f, md = -1e30f;
    for (long long i = (long long)blockIdx.x * blockDim.x + threadIdx.x; i < n;
         i += (long long)gridDim.x * blockDim.x) {
        ms = fmaxf(ms, g_as[i]);
        md = fmaxf(md, g_ad[i]);
    }
#pragma unroll
    for (int off = 16; off; off >>= 1) {
        ms = fmaxf(ms, __shfl_xor_sync(0xffffffffu, ms, off));
        md = fmaxf(md, __shfl_xor_sync(0xffffffffu, md, off));
    }
    __shared__ float sms[8], smd[8];
    int wid = threadIdx.x >> 5;
    if ((threadIdx.x & 31) == 0) { sms[wid] = ms; smd[wid] = md; }
    __syncthreads();
    if (threadIdx.x == 0) {
        for (int i = 1; i < 8; i++) { ms = fmaxf(ms, sms[i]); md = fmaxf(md, smd[i]); }
        atomic_fmax(&g_ms[r], ms);
        atomic_fmax(&g_md[r], md);
    }
}

// ---------------------------------------------------------------------------
// Fused edge pass: 16 lanes per edge (each lane computes e,w redundantly).
// Accumulates numerator (comb, unnormalized) and denominator in one pass.
// exp arg = e - max(ms+md, 0) <= 0 since leaky_relu is monotone.
// ---------------------------------------------------------------------------
__global__ void edge_kernel(int r, int T, int E, int coloff4) {
    int gt   = blockIdx.x * blockDim.x + threadIdx.x;
    int lane = gt & 31;
    int sub  = lane & 15;
    int i    = ((gt >> 5) << 1) + (lane >> 4);
    if (i >= T) return;
    int s, d;
    if (i < E) { int2 e2 = g_e[(size_t)r * MAXE + i]; s = e2.x; d = e2.y; }
    else       { s = d = i - E; }
    float e = g_as[s] + g_ad[d];
    e = e > 0.f ? e : 0.2f * e;
    float mg = fmaxf(__int_as_float(g_ms[r]) + __int_as_float(g_md[r]), 0.f);
    float w = __expf(e - mg);
    if (sub == 0) atomicAdd(&g_den[(size_t)r * MAXN + d], w);

    float4 hv = ((const float4*)g_h)[(size_t)s * 16 + sub];
    float4* dstp = ((float4*)g_comb) + (size_t)d * 80 + coloff4 + sub;
    asm volatile("red.global.add.v4.f32 [%0], {%1,%2,%3,%4};"
                 :: "l"(dstp), "f"(hv.x * w), "f"(hv.y * w),
                    "f"(hv.z * w), "f"(hv.w * w)
                 : "memory");
}

// ---------------------------------------------------------------------------
// Normalize relation slices: comb[:, 64:320] = comb/den + bg
// One float4 per thread: n * 64 float4s over the 4 relation slices.
// ---------------------------------------------------------------------------
__global__ void normalize_kernel(const float* __restrict__ bg_l, int n) {
    long long i = (long long)blockIdx.x * blockDim.x + threadIdx.x;
    if (i >= (long long)n * 64) return;
    int row = (int)(i >> 6);
    int c4  = (int)(i & 63);
    int r   = c4 >> 4;
    float rd = __fdividef(1.f, g_den[(size_t)r * MAXN + row]);
    float4 bv = ((const float4*)bg_l)[c4];
    float4* p = ((float4*)g_comb) + (size_t)row * 80 + 16 + c4;
    float4 v = *p;
    v.x = v.x * rd + bv.x; v.y = v.y * rd + bv.y;
    v.z = v.z * rd + bv.z; v.w = v.w * rd + bv.w;
    *p = v;
}

// ---------------------------------------------------------------------------
// MLP (R1-proven): out = tanh(comb @ W1 + b1) @ W2 + b2
// 512 threads = 8 groups x 64 cols; 64-row tile; 8 rows per thread. 192KB smem.
// ---------------------------------------------------------------------------
__global__ void mlp_kernel(const float* __restrict__ W1,
                           const float* __restrict__ b1,
                           const float* __restrict__ W2,
                           const float* __restrict__ b2,
                           float* __restrict__ outbuf, int last, int n) {
    extern __shared__ float sm[];
    float* W1s   = sm;                    // 320*64
    float* W2s   = W1s + 320 * 64;        // 64*64
    float* combs = W2s + 64 * 64;         // 64*320
    float* hids  = combs + 64 * 320;      // 64*64

    int tid = threadIdx.x;
    int col = tid & 63;
    int g   = tid >> 6;

    for (int i = tid; i < 320 * 64; i += 512) W1s[i] = W1[i];
    for (int i = tid; i < 64 * 64; i += 512)  W2s[i] = W2[i];
    float b1c = b1[col];
    float b2c = b2[col];

    long long base = (long long)blockIdx.x * 64 * 320;
    long long lim  = (long long)n * 320;
    for (int i = tid; i < 64 * 320; i += 512)
        combs[i] = (base + i < lim) ? g_comb[base + i] : 0.f;
    __syncthreads();

    float acc[8];
#pragma unroll
    for (int q = 0; q < 8; q++) acc[q] = 0.f;
    const float4* c4 = (const float4*)(combs + g * 8 * 320);
#pragma unroll 4
    for (int k4 = 0; k4 < 80; k4++) {
        float w0 = W1s[(4 * k4 + 0) * 64 + col];
        float w1 = W1s[(4 * k4 + 1) * 64 + col];
        float w2 = W1s[(4 * k4 + 2) * 64 + col];
        float w3 = W1s[(4 * k4 + 3) * 64 + col];
#pragma unroll
        for (int q = 0; q < 8; q++) {
            float4 cv = c4[q * 80 + k4];
            acc[q] += cv.x * w0 + cv.y * w1 + cv.z * w2 + cv.w * w3;
        }
    }
#pragma unroll
    for (int q = 0; q < 8; q++)
        hids[(g * 8 + q) * 64 + col] = tanhf(acc[q] + b1c);
    __syncthreads();

    float acc2[8];
#pragma unroll
    for (int q = 0; q < 8; q++) acc2[q] = 0.f;
    const float4* h4 = (const float4*)(hids + g * 8 * 64);
#pragma unroll
    for (int k4 = 0; k4 < 16; k4++) {
        float w0 = W2s[(4 * k4 + 0) * 64 + col];
        float w1 = W2s[(4 * k4 + 1) * 64 + col];
        float w2 = W2s[(4 * k4 + 2) * 64 + col];
        float w3 = W2s[(4 * k4 + 3) * 64 + col];
#pragma unroll
        for (int q = 0; q < 8; q++) {
            float4 hv = h4[q * 16 + k4];
            acc2[q] += hv.x * w0 + hv.y * w1 + hv.z * w2 + hv.w * w3;
        }
    }

    float* o = last ? outbuf : g_x;
    int row0 = blockIdx.x * 64 + g * 8;
#pragma unroll
    for (int q = 0; q < 8; q++) {
        int row = row0 + q;
        if (row < n) o[(long long)row * 64 + col] = acc2[q] + b2c;
    }
}

// ---------------------------------------------------------------------------
extern "C" void kernel_launch(void* const* d_in, const int* in_sizes, int n_in,
                              void* d_out, int out_size) {
    const float* x_in  = (const float*)d_in[0];
    const void*  edges = d_in[1];
    const float* Wg    = (const float*)d_in[2];
    const float* a_src = (const float*)d_in[3];
    const float* a_dst = (const float*)d_in[4];
    const float* bg    = (const float*)d_in[5];
    const float* W1    = (const float*)d_in[6];
    const float* b1    = (const float*)d_in[7];
    const float* W2    = (const float*)d_in[8];
    const float* b2    = (const float*)d_in[9];

    int D  = in_sizes[2] / in_sizes[3];
    int LD = in_sizes[7];
    int L  = LD / D;
    int R  = in_sizes[3] / LD;
    int N  = in_sizes[0] / D;
    long long E = (long long)in_sizes[1] / (2 * R);

    cudaFuncSetAttribute(mlp_kernel,
                         cudaFuncAttributeMaxDynamicSharedMemorySize, 196608);

    detect_kernel<<<1, 1>>>((const unsigned int*)edges);
    {
        long long tot = (long long)R * E;
        pack_edges_kernel<<<(int)((tot + 255) / 256), 256>>>(edges, E, R);
    }

    long long nd = (long long)N * DD;
    int nb_nd = (int)((nd + 255) / 256);
    copy_in_kernel<<<nb_nd, 256>>>(x_in, nd);

    int T = (int)E + N;
    long long lanes = (long long)T * 16;
    int nb_edge = (int)((lanes + 255) / 256);
    long long c4tot = (long long)N * 80;
    int nb_comb = (int)((c4tot + 255) / 256);
    int nb_den = (int)(((long long)R * MAXN + 255) / 256);
    int nb_alpha = (N + 255) / 256;
    long long norm_tot = (long long)N * 64;
    int nb_norm = (int)((norm_tot + 255) / 256);
    int nb_gemm = 1480;

    for (int l = 0; l < L; l++) {
        comb_init_kernel<<<nb_comb, 256>>>(N);
        zero_den_kernel<<<nb_den, 256>>>(R);
        for (int r = 0; r < R; r++) {
            zero_alpha_kernel<<<nb_alpha, 256>>>(N);
            gemm_h_kernel<<<nb_gemm, 256>>>(Wg + ((size_t)l * R + r) * D * D,
                                            a_src + ((size_t)l * R + r) * D,
                                            a_dst + ((size_t)l * R + r) * D, N);
            maxred_kernel<<<256, 256>>>(r, N);
            edge_kernel<<<nb_edge, 256>>>(r, T, (int)E, (1 + r) * 16);
        }
        normalize_kernel<<<nb_norm, 256>>>(bg + (size_t)l * R * D, N);
        mlp_kernel<<<(N + 63) / 64, 512, 196608>>>(
            W1 + (size_t)l * 5 * D * D, b1 + (size_t)l * D,
            W2 + (size_t)l * D * D, b2 + (size_t)l * D,
            (float*)d_out, (l == L - 1) ? 1 : 0, N);
    }
}

// round 5
// speedup vs baseline: 1.2515x; 1.1443x over previous
#include <cuda_runtime.h>

// ---------------------------------------------------------------------------
// SDGNN forward. N=100000, D=64, E=1e6, L=2, R=4.
// Per layer: one fused 4-relation GEMM (+alphas), global-shift softmax with
// one fused edge pass (all relations), compact gat buffer, ping-pong x.
// NOTE: __device__ globals are only referenced from device code (flag-based
// selection) — passing their symbols from host was the R2/R4 failure.
// ---------------------------------------------------------------------------

#define MAXN 100000
#define MAXE 1000000
#define DD   64

__device__ __align__(16) float g_x [(size_t)MAXN * DD];        // layer input (ping)
__device__ __align__(16) float g_x2[(size_t)MAXN * DD];        // layer output (pong)
__device__ __align__(16) float g_h [(size_t)4 * MAXN * DD];    // h[r] = x @ Wg[l,r]
__device__ __align__(16) float g_gat[(size_t)MAXN * 4 * DD];   // [row][r*64+c] unnorm GAT
__device__ __align__(16) int2  g_e[(size_t)4 * MAXE];          // packed int32 edges
__device__ float g_as[(size_t)4 * MAXN];
__device__ float g_ad[(size_t)4 * MAXN];
__device__ float g_den[(size_t)4 * MAXN];
__device__ int   g_ms[4];
__device__ int   g_md[4];
__device__ int   g_is64;

// ---------------------------------------------------------------------------
__global__ void detect_kernel(const unsigned int* __restrict__ e) {
    int odd_nonzero = 0;
    for (int i = 1; i < 512; i += 2)
        if (e[i] != 0u) odd_nonzero = 1;
    g_is64 = odd_nonzero ? 0 : 1;
}

__global__ void pack_edges_kernel(const void* __restrict__ edges, long long E, int R) {
    long long i = (long long)blockIdx.x * blockDim.x + threadIdx.x;
    long long tot = (long long)R * E;
    if (i >= tot) return;
    int r = (int)(i / E);
    long long j = i - (long long)r * E;
    int s, d;
    if (g_is64) {
        const long long* p = (const long long*)edges;
        s = (int)p[(long long)(2 * r) * E + j];
        d = (int)p[(long long)(2 * r + 1) * E + j];
    } else {
        const int* p = (const int*)edges;
        s = p[(long long)(2 * r) * E + j];
        d = p[(long long)(2 * r + 1) * E + j];
    }
    g_e[(size_t)r * MAXE + j] = make_int2(s, d);
}

__global__ void copy_in_kernel(const float* __restrict__ xin, long long cnt4) {
    long long i = (long long)blockIdx.x * blockDim.x + threadIdx.x;
    if (i < cnt4) ((float4*)g_x)[i] = ((const float4*)xin)[i];
}

// ---------------------------------------------------------------------------
__global__ void zero_gat_kernel(int n) {
    long long i = (long long)blockIdx.x * blockDim.x + threadIdx.x;
    if (i < (long long)n * 64)
        ((float4*)g_gat)[i] = make_float4(0.f, 0.f, 0.f, 0.f);
}

__global__ void zero_alpha_kernel() {
    long long i = (long long)blockIdx.x * blockDim.x + threadIdx.x;
    if (i < (long long)4 * MAXN) { g_as[i] = 0.f; g_ad[i] = 0.f; }
}

__global__ void zero_den_kernel() {
    long long i = (long long)blockIdx.x * blockDim.x + threadIdx.x;
    if (i < (long long)4 * MAXN) g_den[i] = 0.f;
    if (i < 4) { g_ms[i] = 0xff800000; g_md[i] = 0xff800000; }
}

// ---------------------------------------------------------------------------
// Fused 4-relation GEMM: h[r] = x @ Wg[l,r], alphas via warp-reduce + atomics.
// 256 threads: rel = tid>>6, col = tid&63. 16-row x tile in smem shared by all
// 4 relation groups. src_sel: 0 -> g_x, 1 -> g_x2 (selected in device code).
// ---------------------------------------------------------------------------
__global__ void gemm_all_kernel(int src_sel,
                                const float* __restrict__ Wg_l,
                                const float* __restrict__ as_l,
                                const float* __restrict__ ad_l, int n) {
    const float* xsrc = src_sel ? g_x2 : g_x;
    __shared__ float4 xs[256];   // 16 rows x 16 float4
    int t   = threadIdx.x;
    int col = t & 63;
    int rel = t >> 6;

    float w[DD];
    const float* Wr = Wg_l + (size_t)rel * DD * DD;
#pragma unroll
    for (int k = 0; k < DD; k++) w[k] = Wr[k * DD + col];
    float a_s = as_l[rel * DD + col];
    float a_d = ad_l[rel * DD + col];

    for (long long base = (long long)blockIdx.x * 16; base < n;
         base += (long long)gridDim.x * 16) {
        __syncthreads();
        {
            int lr = t >> 4, lc = t & 15;
            if (base + lr < n)
                xs[t] = ((const float4*)xsrc)[(size_t)(base + lr) * 16 + lc];
        }
        __syncthreads();
        int rows = (n - base < 16) ? (int)(n - base) : 16;
        for (int q = 0; q < rows; q++) {
            float acc = 0.f;
            const float4* xv4 = xs + q * 16;
#pragma unroll
            for (int k4 = 0; k4 < 16; k4++) {
                float4 xv = xv4[k4];
                acc += xv.x * w[4 * k4 + 0] + xv.y * w[4 * k4 + 1] +
                       xv.z * w[4 * k4 + 2] + xv.w * w[4 * k4 + 3];
            }
            long long row = base + q;
            g_h[((size_t)rel * MAXN + row) * DD + col] = acc;

            float vs = acc * a_s;
            float vd = acc * a_d;
#pragma unroll
            for (int off = 16; off; off >>= 1) {
                vs += __shfl_down_sync(0xffffffffu, vs, off);
                vd += __shfl_down_sync(0xffffffffu, vd, off);
            }
            if ((t & 31) == 0) {
                atomicAdd(&g_as[(size_t)rel * MAXN + row], vs);
                atomicAdd(&g_ad[(size_t)rel * MAXN + row], vd);
            }
        }
    }
}

// ---------------------------------------------------------------------------
__device__ __forceinline__ void atomic_fmax(int* addr, float v) {
    if (v >= 0.f) atomicMax(addr, __float_as_int(v));
    else          atomicMin((unsigned int*)addr, __float_as_uint(v));
}

// grid (B, 4): y = relation
__global__ void maxred_kernel(int n) {
    int r = blockIdx.y;
    float ms = -1e30f, md = -1e30f;
    for (long long i = (long long)blockIdx.x * blockDim.x + threadIdx.x; i < n;
         i += (long long)gridDim.x * blockDim.x) {
        ms = fmaxf(ms, g_as[(size_t)r * MAXN + i]);
        md = fmaxf(md, g_ad[(size_t)r * MAXN + i]);
    }
#pragma unroll
    for (int off = 16; off; off >>= 1) {
        ms = fmaxf(ms, __shfl_xor_sync(0xffffffffu, ms, off));
        md = fmaxf(md, __shfl_xor_sync(0xffffffffu, md, off));
    }
    __shared__ float sms[8], smd[8];
    int wid = threadIdx.x >> 5;
    if ((threadIdx.x & 31) == 0) { sms[wid] = ms; smd[wid] = md; }
    __syncthreads();
    if (threadIdx.x == 0) {
        for (int i = 1; i < 8; i++) { ms = fmaxf(ms, sms[i]); md = fmaxf(md, smd[i]); }
        atomic_fmax(&g_ms[r], ms);
        atomic_fmax(&g_md[r], md);
    }
}

// ---------------------------------------------------------------------------
// Fused edge pass, all relations: grid (Bx, 4), 16 lanes per edge.
// exp arg = leaky(e) - max(ms+md, 0) <= 0 (leaky_relu monotone).
// ---------------------------------------------------------------------------
__global__ void edge_kernel(int T, int E) {
    int r    = blockIdx.y;
    int gt   = blockIdx.x * blockDim.x + threadIdx.x;
    int lane = gt & 31;
    int sub  = lane & 15;
    int i    = ((gt >> 5) << 1) + (lane >> 4);
    if (i >= T) return;
    int s, d;
    if (i < E) { int2 e2 = g_e[(size_t)r * MAXE + i]; s = e2.x; d = e2.y; }
    else       { s = d = i - E; }
    float e = g_as[(size_t)r * MAXN + s] + g_ad[(size_t)r * MAXN + d];
    e = e > 0.f ? e : 0.2f * e;
    float mg = fmaxf(__int_as_float(g_ms[r]) + __int_as_float(g_md[r]), 0.f);
    float w = __expf(e - mg);
    if (sub == 0) atomicAdd(&g_den[(size_t)r * MAXN + d], w);

    float4 hv = ((const float4*)g_h)[((size_t)r * MAXN + s) * 16 + sub];
    float4* dstp = ((float4*)g_gat) + (size_t)d * 64 + r * 16 + sub;
    asm volatile("red.global.add.v4.f32 [%0], {%1,%2,%3,%4};"
                 :: "l"(dstp), "f"(hv.x * w), "f"(hv.y * w),
                    "f"(hv.z * w), "f"(hv.w * w)
                 : "memory");
}

// ---------------------------------------------------------------------------
// Normalize gat slices: gat[row, r*64:(r+1)*64] = gat/den[r,row] + bg[r]
// ---------------------------------------------------------------------------
__global__ void normalize_kernel(const float* __restrict__ bg_l, int n) {
    long long i = (long long)blockIdx.x * blockDim.x + threadIdx.x;
    if (i >= (long long)n * 64) return;
    int row = (int)(i >> 6);
    int c4  = (int)(i & 63);
    int r   = c4 >> 4;
    float rd = __fdividef(1.f, g_den[(size_t)r * MAXN + row]);
    float4 bv = ((const float4*)bg_l)[c4];
    float4* p = ((float4*)g_gat) + (size_t)row * 64 + c4;
    float4 v = *p;
    v.x = v.x * rd + bv.x; v.y = v.y * rd + bv.y;
    v.z = v.z * rd + bv.z; v.w = v.w * rd + bv.w;
    *p = v;
}

// ---------------------------------------------------------------------------
// MLP: out = tanh([x | gat] @ W1 + b1) @ W2 + b2
// 512 threads = 8 groups x 64 cols; 64-row tile; 8 rows per thread. 192KB smem.
// src_sel picks ping/pong input in device code; write_out picks d_out vs g_x2.
// ---------------------------------------------------------------------------
__global__ void mlp_kernel(int src_sel, int write_out,
                           const float* __restrict__ W1,
                           const float* __restrict__ b1,
                           const float* __restrict__ W2,
                           const float* __restrict__ b2,
                           float* __restrict__ dout, int n) {
    const float* xsrc = src_sel ? g_x2 : g_x;
    float* o = write_out ? dout : g_x2;

    extern __shared__ float sm[];
    float* W1s   = sm;                    // 320*64
    float* W2s   = W1s + 320 * 64;        // 64*64
    float* combs = W2s + 64 * 64;         // 64*320
    float* hids  = combs + 64 * 320;      // 64*64

    int tid = threadIdx.x;
    int col = tid & 63;
    int g   = tid >> 6;
    int row0 = blockIdx.x * 64;

    for (int i = tid; i < 320 * 64; i += 512) W1s[i] = W1[i];
    for (int i = tid; i < 64 * 64; i += 512)  W2s[i] = W2[i];
    float b1c = b1[col];
    float b2c = b2[col];

    // tile load: 64 rows x 80 float4 (16 from xsrc, 64 from g_gat)
    {
        float4* dst = (float4*)combs;
        for (int i = tid; i < 64 * 80; i += 512) {
            int row = i / 80;
            int c4  = i - row * 80;
            int grow = row0 + row;
            float4 v = make_float4(0.f, 0.f, 0.f, 0.f);
            if (grow < n) {
                if (c4 < 16) v = ((const float4*)xsrc)[(size_t)grow * 16 + c4];
                else         v = ((const float4*)g_gat)[(size_t)grow * 64 + (c4 - 16)];
            }
            dst[i] = v;
        }
    }
    __syncthreads();

    float acc[8];
#pragma unroll
    for (int q = 0; q < 8; q++) acc[q] = 0.f;
    const float4* c4p = (const float4*)(combs + g * 8 * 320);
#pragma unroll 4
    for (int k4 = 0; k4 < 80; k4++) {
        float w0 = W1s[(4 * k4 + 0) * 64 + col];
        float w1 = W1s[(4 * k4 + 1) * 64 + col];
        float w2 = W1s[(4 * k4 + 2) * 64 + col];
        float w3 = W1s[(4 * k4 + 3) * 64 + col];
#pragma unroll
        for (int q = 0; q < 8; q++) {
            float4 cv = c4p[q * 80 + k4];
            acc[q] += cv.x * w0 + cv.y * w1 + cv.z * w2 + cv.w * w3;
        }
    }
#pragma unroll
    for (int q = 0; q < 8; q++)
        hids[(g * 8 + q) * 64 + col] = tanhf(acc[q] + b1c);
    __syncthreads();

    float acc2[8];
#pragma unroll
    for (int q = 0; q < 8; q++) acc2[q] = 0.f;
    const float4* h4 = (const float4*)(hids + g * 8 * 64);
#pragma unroll
    for (int k4 = 0; k4 < 16; k4++) {
        float w0 = W2s[(4 * k4 + 0) * 64 + col];
        float w1 = W2s[(4 * k4 + 1) * 64 + col];
        float w2 = W2s[(4 * k4 + 2) * 64 + col];
        float w3 = W2s[(4 * k4 + 3) * 64 + col];
#pragma unroll
        for (int q = 0; q < 8; q++) {
            float4 hv = h4[q * 16 + k4];
            acc2[q] += hv.x * w0 + hv.y * w1 + hv.z * w2 + hv.w * w3;
        }
    }

    int rbase = row0 + g * 8;
#pragma unroll
    for (int q = 0; q < 8; q++) {
        int row = rbase + q;
        if (row < n) o[(size_t)row * 64 + col] = acc2[q] + b2c;
    }
}

// ---------------------------------------------------------------------------
extern "C" void kernel_launch(void* const* d_in, const int* in_sizes, int n_in,
                              void* d_out, int out_size) {
    const float* x_in  = (const float*)d_in[0];
    const void*  edges = d_in[1];
    const float* Wg    = (const float*)d_in[2];
    const float* a_src = (const float*)d_in[3];
    const float* a_dst = (const float*)d_in[4];
    const float* bg    = (const float*)d_in[5];
    const float* W1    = (const float*)d_in[6];
    const float* b1    = (const float*)d_in[7];
    const float* W2    = (const float*)d_in[8];
    const float* b2    = (const float*)d_in[9];

    int D  = in_sizes[2] / in_sizes[3];
    int LD = in_sizes[7];
    int L  = LD / D;
    int R  = in_sizes[3] / LD;
    int N  = in_sizes[0] / D;
    long long E = (long long)in_sizes[1] / (2 * R);

    cudaFuncSetAttribute(mlp_kernel,
                         cudaFuncAttributeMaxDynamicSharedMemorySize, 196608);

    detect_kernel<<<1, 1>>>((const unsigned int*)edges);                       // 0
    {
        long long tot = (long long)R * E;
        pack_edges_kernel<<<(int)((tot + 255) / 256), 256>>>(edges, E, R);     // 1
    }
    copy_in_kernel<<<(int)(((long long)N * 16 + 255) / 256), 256>>>(           // 2
        x_in, (long long)N * 16);

    int T = (int)E + N;
    int nb_edge = (int)(((long long)T * 16 + 255) / 256);
    int nb_gat  = (int)(((long long)N * 64 + 255) / 256);
    int nb_4n   = (int)(((long long)4 * MAXN + 255) / 256);

    for (int l = 0; l < L; l++) {
        int src_sel   = (l == 0) ? 0 : 1;
        int write_out = (l == L - 1) ? 1 : 0;

        zero_gat_kernel<<<nb_gat, 256>>>(N);        // l0: 3
        zero_alpha_kernel<<<nb_4n, 256>>>();        // l0: 4
        gemm_all_kernel<<<1184, 256>>>(src_sel,     // l0: 5  <- ncu -s 5
                                       Wg + (size_t)l * R * D * D,
                                       a_src + (size_t)l * R * D,
                                       a_dst + (size_t)l * R * D, N);
        zero_den_kernel<<<nb_4n, 256>>>();
        maxred_kernel<<<dim3(64, 4), 256>>>(N);
        edge_kernel<<<dim3(nb_edge, 4), 256>>>(T, (int)E);
        normalize_kernel<<<nb_gat, 256>>>(bg + (size_t)l * R * D, N);
        mlp_kernel<<<(N + 63) / 64, 512, 196608>>>(
            src_sel, write_out,
            W1 + (size_t)l * 5 * D * D, b1 + (size_t)l * D,
            W2 + (size_t)l * D * D, b2 + (size_t)l * D,
            (float*)d_out, N);
    }
}

// round 6
// speedup vs baseline: 1.8014x; 1.4394x over previous
#include <cuda_runtime.h>

// ---------------------------------------------------------------------------
// SDGNN forward. N=100000, D=64, E=1e6, L=2, R=4.
// CSR-gather edge phase (built once per call, reused by both layers):
//   pack+hist -> scan -> scatter -> per-dst gather (no atomics, fused bias+norm)
// gemm_all computes h + alphas (plain stores) + per-relation global max.
// __device__ globals only referenced from device code (R2/R4 lesson).
// ---------------------------------------------------------------------------

#define MAXN 100000
#define MAXE 1000000
#define DD   64
#define TOT  (4 * MAXN)          // hist/rp entries across 4 relations
#define NB1  ((TOT + 1023) / 1024)

__device__ __align__(16) float g_x [(size_t)MAXN * DD];       // layer input (ping)
__device__ __align__(16) float g_x2[(size_t)MAXN * DD];       // layer output (pong)
__device__ __align__(16) float g_h [(size_t)4 * MAXN * DD];   // h[r] = x @ Wg[l,r]
__device__ __align__(16) float g_gat[(size_t)MAXN * 4 * DD];  // [row][r*64+c] GAT out
__device__ __align__(16) int2  g_e[(size_t)4 * MAXE];         // packed int32 edges
__device__ int   g_eidx[(size_t)4 * MAXE];                    // CSR: src per slot
__device__ int   g_hist[TOT];
__device__ int   g_scan[TOT];
__device__ int   g_rp[TOT + 1];                               // CSR row pointers
__device__ int   g_cur[TOT];                                  // scatter cursors
__device__ int   g_bsum[NB1];
__device__ int   g_boff[NB1];
__device__ float g_as[(size_t)4 * MAXN];
__device__ float g_ad[(size_t)4 * MAXN];
__device__ int   g_ms[4];
__device__ int   g_md[4];
__device__ int   g_is64;

// ---------------------------------------------------------------------------
__global__ void detect_kernel(const unsigned int* __restrict__ e) {
    int odd_nonzero = 0;
    for (int i = 1; i < 512; i += 2)
        if (e[i] != 0u) odd_nonzero = 1;
    g_is64 = odd_nonzero ? 0 : 1;
}

__global__ void zero_hist_kernel() {
    int i = blockIdx.x * blockDim.x + threadIdx.x;
    if (i < TOT) g_hist[i] = 0;
}

// pack edges to int32 int2 + destination histogram
__global__ void pack_hist_kernel(const void* __restrict__ edges, long long E, int R) {
    long long i = (long long)blockIdx.x * blockDim.x + threadIdx.x;
    long long tot = (long long)R * E;
    if (i >= tot) return;
    int r = (int)(i / E);
    long long j = i - (long long)r * E;
    int s, d;
    if (g_is64) {
        const long long* p = (const long long*)edges;
        s = (int)p[(long long)(2 * r) * E + j];
        d = (int)p[(long long)(2 * r + 1) * E + j];
    } else {
        const int* p = (const int*)edges;
        s = p[(long long)(2 * r) * E + j];
        d = p[(long long)(2 * r + 1) * E + j];
    }
    g_e[(size_t)r * MAXE + j] = make_int2(s, d);
    atomicAdd(&g_hist[r * MAXN + d], 1);
}

// ---------------------------------------------------------------------------
// Two-level exclusive scan of g_hist (TOT elements).
// S1: 1024-elem blocks -> inclusive per-element g_scan + block totals g_bsum.
// ---------------------------------------------------------------------------
__global__ void scan1_kernel() {
    __shared__ int sbuf[2][256];
    int t = threadIdx.x;
    int b = blockIdx.x;
    int base = b * 1024 + t * 4;
    int v0 = (base + 0 < TOT) ? g_hist[base + 0] : 0;
    int v1 = (base + 1 < TOT) ? g_hist[base + 1] : 0;
    int v2 = (base + 2 < TOT) ? g_hist[base + 2] : 0;
    int v3 = (base + 3 < TOT) ? g_hist[base + 3] : 0;
    int p0 = v0, p1 = p0 + v1, p2 = p1 + v2, p3 = p2 + v3;

    // Hillis-Steele inclusive scan of thread totals (double buffer)
    int cur = 0;
    sbuf[0][t] = p3;
    __syncthreads();
    for (int off = 1; off < 256; off <<= 1) {
        int v = sbuf[cur][t];
        if (t >= off) v += sbuf[cur][t - off];
        sbuf[1 - cur][t] = v;
        cur = 1 - cur;
        __syncthreads();
    }
    int incl = sbuf[cur][t];
    int offset = incl - p3;   // exclusive
    if (base + 0 < TOT) g_scan[base + 0] = offset + p0;
    if (base + 1 < TOT) g_scan[base + 1] = offset + p1;
    if (base + 2 < TOT) g_scan[base + 2] = offset + p2;
    if (base + 3 < TOT) g_scan[base + 3] = offset + p3;
    if (t == 255) g_bsum[b] = incl;
}

// S2: single block scans NB1 block totals -> exclusive g_boff
__global__ void scan2_kernel() {
    __shared__ int sbuf[2][512];
    int t = threadIdx.x;
    int v = (t < NB1) ? g_bsum[t] : 0;
    int cur = 0;
    sbuf[0][t] = v;
    __syncthreads();
    for (int off = 1; off < 512; off <<= 1) {
        int x = sbuf[cur][t];
        if (t >= off) x += sbuf[cur][t - off];
        sbuf[1 - cur][t] = x;
        cur = 1 - cur;
        __syncthreads();
    }
    if (t < NB1) g_boff[t] = sbuf[cur][t] - v;
}

// S3: finalize row pointers + scatter cursors
__global__ void scan3_kernel() {
    int i = blockIdx.x * blockDim.x + threadIdx.x;
    if (i >= TOT) return;
    int incl = g_scan[i] + g_boff[i >> 10];
    g_rp[i + 1] = incl;
    g_cur[i] = incl - g_hist[i];
    if (i == 0) g_rp[0] = 0;
}

// scatter: g_eidx[slot] = src, slots ordered by (rel, dst)
__global__ void scatter_kernel(long long E, int R) {
    long long i = (long long)blockIdx.x * blockDim.x + threadIdx.x;
    long long tot = (long long)R * E;
    if (i >= tot) return;
    int r = (int)(i / E);
    long long j = i - (long long)r * E;
    int2 e2 = g_e[(size_t)r * MAXE + j];
    int pos = atomicAdd(&g_cur[r * MAXN + e2.y], 1);
    g_eidx[pos] = e2.x;
}

// ---------------------------------------------------------------------------
__global__ void copy_in_kernel(const float* __restrict__ xin, long long cnt4) {
    long long i = (long long)blockIdx.x * blockDim.x + threadIdx.x;
    if (i < cnt4) ((float4*)g_x)[i] = ((const float4*)xin)[i];
    if (i < 4) { g_ms[i] = 0xff800000; g_md[i] = 0xff800000; }
}

// ---------------------------------------------------------------------------
__device__ __forceinline__ void atomic_fmax(int* addr, float v) {
    if (v >= 0.f) atomicMax(addr, __float_as_int(v));
    else          atomicMin((unsigned int*)addr, __float_as_uint(v));
}

// ---------------------------------------------------------------------------
// Fused 4-relation GEMM: h[r] = x @ Wg[l,r]. Alphas combined via smem (plain
// stores), block-local running max -> one atomic_fmax per block per relation.
// 256 threads: rel = tid>>6, col = tid&63; 16-row x tile shared by all rels.
// ---------------------------------------------------------------------------
__global__ void gemm_all_kernel(int src_sel,
                                const float* __restrict__ Wg_l,
                                const float* __restrict__ as_l,
                                const float* __restrict__ ad_l, int n) {
    const float* xsrc = src_sel ? g_x2 : g_x;
    __shared__ float4 xs[256];            // 16 rows x 16 float4
    __shared__ float pal[4][16][2][2];    // [rel][row][warpHalf][s/d]
    __shared__ float smx[64][2];
    int t   = threadIdx.x;
    int col = t & 63;
    int rel = t >> 6;
    int half = (t >> 5) & 1;

    float w[DD];
    const float* Wr = Wg_l + (size_t)rel * DD * DD;
#pragma unroll
    for (int k = 0; k < DD; k++) w[k] = Wr[k * DD + col];
    float a_s = as_l[rel * DD + col];
    float a_d = ad_l[rel * DD + col];

    float lms = -1e30f, lmd = -1e30f;     // tracked by t<64 combine threads
    int crel = t >> 4, crow = t & 15;     // combine mapping

    for (long long base = (long long)blockIdx.x * 16; base < n;
         base += (long long)gridDim.x * 16) {
        __syncthreads();
        {
            int lr = t >> 4, lc = t & 15;
            if (base + lr < n)
                xs[t] = ((const float4*)xsrc)[(size_t)(base + lr) * 16 + lc];
        }
        __syncthreads();
        int rows = (n - base < 16) ? (int)(n - base) : 16;
        for (int q = 0; q < rows; q++) {
            float acc = 0.f;
            const float4* xv4 = xs + q * 16;
#pragma unroll
            for (int k4 = 0; k4 < 16; k4++) {
                float4 xv = xv4[k4];
                acc += xv.x * w[4 * k4 + 0] + xv.y * w[4 * k4 + 1] +
                       xv.z * w[4 * k4 + 2] + xv.w * w[4 * k4 + 3];
            }
            long long row = base + q;
            g_h[((size_t)rel * MAXN + row) * DD + col] = acc;

            float vs = acc * a_s;
            float vd = acc * a_d;
#pragma unroll
            for (int off = 16; off; off >>= 1) {
                vs += __shfl_down_sync(0xffffffffu, vs, off);
                vd += __shfl_down_sync(0xffffffffu, vd, off);
            }
            if ((t & 31) == 0) {
                pal[rel][q][half][0] = vs;
                pal[rel][q][half][1] = vd;
            }
        }
        __syncthreads();
        if (t < 64 && crow < rows) {
            long long row = base + crow;
            float as = pal[crel][crow][0][0] + pal[crel][crow][1][0];
            float ad = pal[crel][crow][0][1] + pal[crel][crow][1][1];
            g_as[(size_t)crel * MAXN + row] = as;
            g_ad[(size_t)crel * MAXN + row] = ad;
            lms = fmaxf(lms, as);
            lmd = fmaxf(lmd, ad);
        }
    }

    __syncthreads();
    if (t < 64) { smx[t][0] = lms; smx[t][1] = lmd; }
    __syncthreads();
    if (t < 4) {
        float a = -1e30f, b = -1e30f;
        for (int k = 0; k < 16; k++) {
            a = fmaxf(a, smx[t * 16 + k][0]);
            b = fmaxf(b, smx[t * 16 + k][1]);
        }
        atomic_fmax(&g_ms[t], a);
        atomic_fmax(&g_md[t], b);
    }
}

// ---------------------------------------------------------------------------
// CSR gather: grid (ceil(n/16), 4); 256 thr = 16 groups x 16 lanes.
// Group owns one dst: acc = sum_w w*h[s] (incl self loop), den = sum w.
// Writes gat[d][r*64..] = acc/den + bg — no atomics, bias+normalize fused.
// ---------------------------------------------------------------------------
__global__ void gather_kernel(const float* __restrict__ bg_l, int n) {
    int r    = blockIdx.y;
    int grp  = threadIdx.x >> 4;
    int lane = threadIdx.x & 15;
    int d = blockIdx.x * 16 + grp;
    if (d >= n) return;

    float mg = fmaxf(__int_as_float(g_ms[r]) + __int_as_float(g_md[r]), 0.f);
    float ad_d = g_ad[(size_t)r * MAXN + d];
    const float4* h4 = (const float4*)g_h;

    // self loop
    float e = g_as[(size_t)r * MAXN + d] + ad_d;
    e = e > 0.f ? e : 0.2f * e;
    float wv = __expf(e - mg);
    float den = wv;
    float4 hv = h4[((size_t)r * MAXN + d) * 16 + lane];
    float4 acc = make_float4(hv.x * wv, hv.y * wv, hv.z * wv, hv.w * wv);

    int start = g_rp[r * MAXN + d];
    int end   = g_rp[r * MAXN + d + 1];
    for (int j = start; j < end; j++) {
        int s = g_eidx[j];
        float es = g_as[(size_t)r * MAXN + s] + ad_d;
        es = es > 0.f ? es : 0.2f * es;
        float ww = __expf(es - mg);
        den += ww;
        float4 hs = h4[((size_t)r * MAXN + s) * 16 + lane];
        acc.x += hs.x * ww; acc.y += hs.y * ww;
        acc.z += hs.z * ww; acc.w += hs.w * ww;
    }
    float rd = __fdividef(1.f, den);
    float4 bv = ((const float4*)bg_l)[r * 16 + lane];
    acc.x = acc.x * rd + bv.x; acc.y = acc.y * rd + bv.y;
    acc.z = acc.z * rd + bv.z; acc.w = acc.w * rd + bv.w;
    ((float4*)g_gat)[(size_t)d * 64 + r * 16 + lane] = acc;
}

// ---------------------------------------------------------------------------
// MLP: out = tanh([x | gat] @ W1 + b1) @ W2 + b2  (unchanged from R5)
// Epilogue: block 0 resets g_ms/g_md for the next layer's gemm.
// ---------------------------------------------------------------------------
__global__ void mlp_kernel(int src_sel, int write_out,
                           const float* __restrict__ W1,
                           const float* __restrict__ b1,
                           const float* __restrict__ W2,
                           const float* __restrict__ b2,
                           float* __restrict__ dout, int n) {
    const float* xsrc = src_sel ? g_x2 : g_x;
    float* o = write_out ? dout : g_x2;

    extern __shared__ float sm[];
    float* W1s   = sm;                    // 320*64
    float* W2s   = W1s + 320 * 64;        // 64*64
    float* combs = W2s + 64 * 64;         // 64*320
    float* hids  = combs + 64 * 320;      // 64*64

    int tid = threadIdx.x;
    int col = tid & 63;
    int g   = tid >> 6;
    int row0 = blockIdx.x * 64;

    if (blockIdx.x == 0 && tid < 4) {
        g_ms[tid] = 0xff800000;
        g_md[tid] = 0xff800000;
    }

    for (int i = tid; i < 320 * 64; i += 512) W1s[i] = W1[i];
    for (int i = tid; i < 64 * 64; i += 512)  W2s[i] = W2[i];
    float b1c = b1[col];
    float b2c = b2[col];

    {
        float4* dst = (float4*)combs;
        for (int i = tid; i < 64 * 80; i += 512) {
            int row = i / 80;
            int c4  = i - row * 80;
            int grow = row0 + row;
            float4 v = make_float4(0.f, 0.f, 0.f, 0.f);
            if (grow < n) {
                if (c4 < 16) v = ((const float4*)xsrc)[(size_t)grow * 16 + c4];
                else         v = ((const float4*)g_gat)[(size_t)grow * 64 + (c4 - 16)];
            }
            dst[i] = v;
        }
    }
    __syncthreads();

    float acc[8];
#pragma unroll
    for (int q = 0; q < 8; q++) acc[q] = 0.f;
    const float4* c4p = (const float4*)(combs + g * 8 * 320);
#pragma unroll 4
    for (int k4 = 0; k4 < 80; k4++) {
        float w0 = W1s[(4 * k4 + 0) * 64 + col];
        float w1 = W1s[(4 * k4 + 1) * 64 + col];
        float w2 = W1s[(4 * k4 + 2) * 64 + col];
        float w3 = W1s[(4 * k4 + 3) * 64 + col];
#pragma unroll
        for (int q = 0; q < 8; q++) {
            float4 cv = c4p[q * 80 + k4];
            acc[q] += cv.x * w0 + cv.y * w1 + cv.z * w2 + cv.w * w3;
        }
    }
#pragma unroll
    for (int q = 0; q < 8; q++)
        hids[(g * 8 + q) * 64 + col] = tanhf(acc[q] + b1c);
    __syncthreads();

    float acc2[8];
#pragma unroll
    for (int q = 0; q < 8; q++) acc2[q] = 0.f;
    const float4* h4 = (const float4*)(hids + g * 8 * 64);
#pragma unroll
    for (int k4 = 0; k4 < 16; k4++) {
        float w0 = W2s[(4 * k4 + 0) * 64 + col];
        float w1 = W2s[(4 * k4 + 1) * 64 + col];
        float w2 = W2s[(4 * k4 + 2) * 64 + col];
        float w3 = W2s[(4 * k4 + 3) * 64 + col];
#pragma unroll
        for (int q = 0; q < 8; q++) {
            float4 hv = h4[q * 16 + k4];
            acc2[q] += hv.x * w0 + hv.y * w1 + hv.z * w2 + hv.w * w3;
        }
    }

    int rbase = row0 + g * 8;
#pragma unroll
    for (int q = 0; q < 8; q++) {
        int row = rbase + q;
        if (row < n) o[(size_t)row * 64 + col] = acc2[q] + b2c;
    }
}

// ---------------------------------------------------------------------------
extern "C" void kernel_launch(void* const* d_in, const int* in_sizes, int n_in,
                              void* d_out, int out_size) {
    const float* x_in  = (const float*)d_in[0];
    const void*  edges = d_in[1];
    const float* Wg    = (const float*)d_in[2];
    const float* a_src = (const float*)d_in[3];
    const float* a_dst = (const float*)d_in[4];
    const float* bg    = (const float*)d_in[5];
    const float* W1    = (const float*)d_in[6];
    const float* b1    = (const float*)d_in[7];
    const float* W2    = (const float*)d_in[8];
    const float* b2    = (const float*)d_in[9];

    int D  = in_sizes[2] / in_sizes[3];
    int LD = in_sizes[7];
    int L  = LD / D;
    int R  = in_sizes[3] / LD;
    int N  = in_sizes[0] / D;
    long long E = (long long)in_sizes[1] / (2 * R);

    cudaFuncSetAttribute(mlp_kernel,
                         cudaFuncAttributeMaxDynamicSharedMemorySize, 196608);

    long long tot = (long long)R * E;
    int nb_tot  = (int)((tot + 255) / 256);
    int nb_hist = (TOT + 255) / 256;

    detect_kernel<<<1, 1>>>((const unsigned int*)edges);
    zero_hist_kernel<<<nb_hist, 256>>>();
    pack_hist_kernel<<<nb_tot, 256>>>(edges, E, R);
    scan1_kernel<<<NB1, 256>>>();
    scan2_kernel<<<1, 512>>>();
    scan3_kernel<<<nb_hist, 256>>>();
    scatter_kernel<<<nb_tot, 256>>>(E, R);
    copy_in_kernel<<<(int)(((long long)N * 16 + 255) / 256), 256>>>(
        x_in, (long long)N * 16);

    int nb_gather = (N + 15) / 16;

    for (int l = 0; l < L; l++) {
        int src_sel   = (l == 0) ? 0 : 1;
        int write_out = (l == L - 1) ? 1 : 0;

        gemm_all_kernel<<<1184, 256>>>(src_sel,
                                       Wg + (size_t)l * R * D * D,
                                       a_src + (size_t)l * R * D,
                                       a_dst + (size_t)l * R * D, N);
        gather_kernel<<<dim3(nb_gather, 4), 256>>>(bg + (size_t)l * R * D, N);
        mlp_kernel<<<(N + 63) / 64, 512, 196608>>>(
            src_sel, write_out,
            W1 + (size_t)l * 5 * D * D, b1 + (size_t)l * D,
            W2 + (size_t)l * D * D, b2 + (size_t)l * D,
            (float*)d_out, N);
    }
}